// round 8
// baseline (speedup 1.0000x reference)
#include <cuda_runtime.h>
#include <cstdint>

#define BATCH 32
#define T     1024
#define DIN   512
#define DH    512
#define M_TOT (BATCH * T)   // 32768
#define PLANE ((size_t)M_TOT * DIN)

__device__ unsigned char g_Cq[3 * PLANE];
__device__ unsigned char g_Wq[3 * (size_t)DH * DIN];

#define WLCAP 262144
__device__ int g_cnt;
__device__ int g_wl[WLCAP];

#define SC_A 1048576.0f     // 2^20
#define SC_W 67108864.0f    // 2^26
#define CLAMP_V 8300000
#define TWO38F 274877906944.0f
#define DELTA38 13743895LL   // 5e-5 * 2^38

// ---------------------------------------------------------------------------
__device__ __forceinline__ uint32_t smem_u32(const void* p) {
    uint32_t a;
    asm("{ .reg .u64 t; cvta.to.shared.u64 t, %1; cvt.u32.u64 %0, t; }"
        : "=r"(a) : "l"(p));
    return a;
}
#define CP_ASYNC16(sa, gp) \
    asm volatile("cp.async.cg.shared.global [%0], [%1], 16;" :: "r"(sa), "l"(gp))
#define CP_COMMIT() asm volatile("cp.async.commit_group;" ::: "memory")
#define CP_WAIT(n)  asm volatile("cp.async.wait_group %0;" :: "n"(n) : "memory")

__device__ __forceinline__ void imma_k32(int c[4], const uint32_t a[4], const uint32_t b[2]) {
    asm volatile(
        "mma.sync.aligned.m16n8k32.row.col.s32.s8.s8.s32 "
        "{%0,%1,%2,%3}, {%4,%5,%6,%7}, {%8,%9}, {%0,%1,%2,%3};"
        : "+r"(c[0]), "+r"(c[1]), "+r"(c[2]), "+r"(c[3])
        : "r"(a[0]), "r"(a[1]), "r"(a[2]), "r"(a[3]), "r"(b[0]), "r"(b[1]));
}

__device__ __forceinline__ void split3(int v, int& l0, int& l1, int& l2) {
    l0 = (int)(signed char)(v & 0xFF);
    int v1 = (v - l0) >> 8;
    l1 = (int)(signed char)(v1 & 0xFF);
    l2 = (v1 - l1) >> 8;
}

__global__ void zero_cnt() { g_cnt = 0; }

// ---------------------------------------------------------------------------
// conv + quantize + limb-split (fast path input prep)
// ---------------------------------------------------------------------------
__global__ __launch_bounds__(128)
void conv_quant(const float* __restrict__ X)
{
    const int b     = blockIdx.x >> 3;
    const int chunk = blockIdx.x & 7;
    const int i0    = threadIdx.x * 4;

    const float AL  = 0.36787944117144233f;
    const float OMB = 1.0f - AL;

    const float* xp = X + (size_t)b * T * DIN + i0;
    const int t0 = chunk * 128;
    const int w0 = (t0 >= 64) ? (t0 - 64) : 0;

    float s[4] = {0,0,0,0}, m[4] = {0,0,0,0};

    for (int t = w0; t < t0; t += 4) {
#pragma unroll
        for (int u = 0; u < 4; u++) {
            float4 x4 = *(const float4*)(xp + (size_t)(t + u) * DIN);
            float xx[4] = {x4.x, x4.y, x4.z, x4.w};
#pragma unroll
            for (int q = 0; q < 4; q++) {
                s[q] = fmaf(AL, s[q], xx[q]);
                m[q] = fmaf(AL, m[q], OMB * s[q]);
            }
        }
    }
    for (int t = t0; t < t0 + 128; t += 4) {
#pragma unroll
        for (int u = 0; u < 4; u++) {
            float4 x4 = *(const float4*)(xp + (size_t)(t + u) * DIN);
            float xx[4] = {x4.x, x4.y, x4.z, x4.w};
            uchar4 p0, p1, p2;
            unsigned char* pb0 = &p0.x;
            unsigned char* pb1 = &p1.x;
            unsigned char* pb2 = &p2.x;
#pragma unroll
            for (int q = 0; q < 4; q++) {
                s[q] = fmaf(AL, s[q], xx[q]);
                m[q] = fmaf(AL, m[q], OMB * s[q]);
                int v = __float2int_rn(m[q] * SC_A);
                v = max(min(v, CLAMP_V), -CLAMP_V);
                int l0, l1, l2; split3(v, l0, l1, l2);
                pb0[q] = (unsigned char)(l0 & 0xFF);
                pb1[q] = (unsigned char)(l1 & 0xFF);
                pb2[q] = (unsigned char)(l2 & 0xFF);
            }
            size_t idx = ((size_t)b * T + (t + u)) * DIN + i0;
            *(uchar4*)(g_Cq + 0 * PLANE + idx) = p0;
            *(uchar4*)(g_Cq + 1 * PLANE + idx) = p1;
            *(uchar4*)(g_Cq + 2 * PLANE + idx) = p2;
        }
    }
}

__global__ __launch_bounds__(128)
void w_quant(const float* __restrict__ W)
{
    const size_t WPL = (size_t)DH * DIN;
    size_t idx = ((size_t)blockIdx.x * 128 + threadIdx.x) * 4;
    float4 w4 = *(const float4*)(W + idx);
    float ww[4] = {w4.x, w4.y, w4.z, w4.w};
    uchar4 p0, p1, p2;
    unsigned char* pb0 = &p0.x;
    unsigned char* pb1 = &p1.x;
    unsigned char* pb2 = &p2.x;
#pragma unroll
    for (int q = 0; q < 4; q++) {
        int v = __float2int_rn(ww[q] * SC_W);
        v = max(min(v, CLAMP_V), -CLAMP_V);
        int l0, l1, l2; split3(v, l0, l1, l2);
        pb0[q] = (unsigned char)(l0 & 0xFF);
        pb1[q] = (unsigned char)(l1 & 0xFF);
        pb2[q] = (unsigned char)(l2 & 0xFF);
    }
    *(uchar4*)(g_Wq + 0 * WPL + idx) = p0;
    *(uchar4*)(g_Wq + 1 * WPL + idx) = p1;
    *(uchar4*)(g_Wq + 2 * WPL + idx) = p2;
}

// ---------------------------------------------------------------------------
// Exact int-limb GEMM + threshold + borderline flagging
// ---------------------------------------------------------------------------
#define NSLICE  16
#define SROWB   48
#define A_PL    (128 * SROWB)
#define B_PL    (64 * SROWB)
#define ABUF    (3 * A_PL)
#define BBUF    (3 * B_PL)
#define BUF_B   (ABUF + BBUF)
#define SMEM_BYTES (2 * BUF_B)

__device__ __forceinline__ void issue_slice(uint32_t sbuf, int bm, int bn,
                                            int k0, int tid)
{
    const unsigned char* gA = g_Cq;
    const unsigned char* gB = g_Wq;
    const size_t WPL = (size_t)DH * DIN;
#pragma unroll
    for (int q = 0; q < 5; q++) {
        int u = tid + q * 256;
        if (u < 768) {
            int p = u >> 8, r = (u >> 1) & 127, h = u & 1;
            CP_ASYNC16(sbuf + p * A_PL + r * SROWB + h * 16,
                       gA + p * PLANE + (size_t)(bm + r) * DIN + k0 + h * 16);
        } else if (u < 1152) {
            int u2 = u - 768;
            int p = u2 >> 7, r = (u2 >> 1) & 63, h = u2 & 1;
            CP_ASYNC16(sbuf + ABUF + p * B_PL + r * SROWB + h * 16,
                       gB + p * WPL + (size_t)(bn + r) * DIN + k0 + h * 16);
        }
    }
}

__device__ __forceinline__ float cumw(int t) {
    const float inv1 = 1.5819767068693265f;   // 1/(1-e^-1)
    float e1 = __expf(-(float)(t + 1));
    float e2 = __expf(-(float)(t + 2));
    return (1.0f - (float)(t + 2) * e1 + (float)(t + 1) * e2) * inv1;
}

__device__ __forceinline__ float spike_flag(long long S, long long R, int lin) {
    long long d = S - R;
    if (d < DELTA38 && d > -DELTA38) {
        int idx = atomicAdd(&g_cnt, 1);
        if (idx < WLCAP) g_wl[idx] = lin;
    }
    return (d > 0) ? 1.0f : 0.0f;
}

__global__ __launch_bounds__(256)
void gemm_int(const float* __restrict__ bias, const float* __restrict__ thr_p,
              float* __restrict__ OUT)
{
    extern __shared__ unsigned char sm[];
    const int tid  = threadIdx.x;
    const int lane = tid & 31;
    const int wid  = tid >> 5;
    const int g    = lane >> 2;
    const int tg   = lane & 3;
    const int wm   = wid >> 1;
    const int wn   = wid & 1;
    const int bm   = blockIdx.x * 128;
    const int bn   = blockIdx.y * 64;

    const uint32_t sb0 = smem_u32(sm);

    int acc4[2][4][4], acc3[2][4][4], acc2[2][4][4], acc1[2][4][4];
#pragma unroll
    for (int i = 0; i < 2; i++)
#pragma unroll
        for (int j = 0; j < 4; j++)
#pragma unroll
            for (int r = 0; r < 4; r++) {
                acc4[i][j][r] = 0; acc3[i][j][r] = 0;
                acc2[i][j][r] = 0; acc1[i][j][r] = 0;
            }

    issue_slice(sb0, bm, bn, 0, tid);
    CP_COMMIT();

    for (int c = 0; c < NSLICE; c++) {
        if (c + 1 < NSLICE) {
            issue_slice(sb0 + ((c + 1) & 1) * BUF_B, bm, bn, (c + 1) * 32, tid);
            CP_COMMIT();
            CP_WAIT(1);
        } else {
            CP_WAIT(0);
        }
        __syncthreads();

        const unsigned char* Ab = sm + (c & 1) * BUF_B;
        const unsigned char* Bb = Ab + ABUF;

        uint32_t afr[2][3][4], bfr[4][3][2];
#pragma unroll
        for (int i = 0; i < 2; i++) {
            int r0 = wm * 32 + i * 16 + g;
#pragma unroll
            for (int p = 0; p < 3; p++) {
                const unsigned char* base = Ab + p * A_PL;
                afr[i][p][0] = *(const uint32_t*)(base + (r0    ) * SROWB + tg * 4);
                afr[i][p][1] = *(const uint32_t*)(base + (r0 + 8) * SROWB + tg * 4);
                afr[i][p][2] = *(const uint32_t*)(base + (r0    ) * SROWB + 16 + tg * 4);
                afr[i][p][3] = *(const uint32_t*)(base + (r0 + 8) * SROWB + 16 + tg * 4);
            }
        }
#pragma unroll
        for (int j = 0; j < 4; j++) {
            int n = wn * 32 + j * 8 + g;
#pragma unroll
            for (int p = 0; p < 3; p++) {
                const unsigned char* base = Bb + p * B_PL;
                bfr[j][p][0] = *(const uint32_t*)(base + n * SROWB + tg * 4);
                bfr[j][p][1] = *(const uint32_t*)(base + n * SROWB + 16 + tg * 4);
            }
        }

#pragma unroll
        for (int i = 0; i < 2; i++)
#pragma unroll
            for (int j = 0; j < 4; j++) {
                imma_k32(acc4[i][j], afr[i][2], bfr[j][2]);
                imma_k32(acc3[i][j], afr[i][2], bfr[j][1]);
                imma_k32(acc3[i][j], afr[i][1], bfr[j][2]);
                imma_k32(acc2[i][j], afr[i][2], bfr[j][0]);
                imma_k32(acc2[i][j], afr[i][1], bfr[j][1]);
                imma_k32(acc2[i][j], afr[i][0], bfr[j][2]);
                imma_k32(acc1[i][j], afr[i][1], bfr[j][0]);
                imma_k32(acc1[i][j], afr[i][0], bfr[j][1]);
            }
        __syncthreads();
    }

    const float thr = thr_p[0];
#pragma unroll
    for (int i = 0; i < 2; i++) {
        int row0 = bm + wm * 32 + i * 16 + g;
        int row1 = row0 + 8;
        float cw0 = cumw(row0 & (T - 1));
        float cw1 = cumw(row1 & (T - 1));
#pragma unroll
        for (int j = 0; j < 4; j++) {
            int col = bn + wn * 32 + j * 8 + tg * 2;
            float b0 = bias[col], b1 = bias[col + 1];
            long long S[4];
#pragma unroll
            for (int r = 0; r < 4; r++) {
                long long s64 = (long long)acc4[i][j][r];
                s64 = (s64 << 8) + (long long)acc3[i][j][r];
                s64 = (s64 << 8) + (long long)acc2[i][j][r];
                s64 = (s64 << 8) + (long long)acc1[i][j][r];
                S[r] = s64;
            }
            long long R00 = __float2ll_rd(fmaf(-b0, cw0, thr) * TWO38F);
            long long R10 = __float2ll_rd(fmaf(-b1, cw0, thr) * TWO38F);
            long long R01 = __float2ll_rd(fmaf(-b0, cw1, thr) * TWO38F);
            long long R11 = __float2ll_rd(fmaf(-b1, cw1, thr) * TWO38F);
            float2 v0, v1;
            v0.x = spike_flag(S[0], R00, row0 * DH + col);
            v0.y = spike_flag(S[1], R10, row0 * DH + col + 1);
            v1.x = spike_flag(S[2], R01, row1 * DH + col);
            v1.y = spike_flag(S[3], R11, row1 * DH + col + 1);
            *(float2*)(OUT + (size_t)row0 * DH + col) = v0;
            *(float2*)(OUT + (size_t)row1 * DH + col) = v1;
        }
    }
}

// ---------------------------------------------------------------------------
// Patch: recompute flagged elements with the R1-exact float-op sequence.
// One warp per item. Dots: sequential fmaf over k=0..511 (ascending, .x..w),
// + bias (plain add). Scan: s=fmaf(AL,s,x); m=fmaf(AL,m,OMB*s) from 80-step
// zero-state warmup (bitwise-equal to full scan w.p. 1-1e-20).
// ---------------------------------------------------------------------------
__global__ __launch_bounds__(256)
void patch(const float* __restrict__ X, const float* __restrict__ W,
           const float* __restrict__ bias, const float* __restrict__ thr_p,
           float* __restrict__ OUT)
{
    const int nwarp = gridDim.x * 8;
    const int w     = blockIdx.x * 8 + (threadIdx.x >> 5);
    const int lane  = threadIdx.x & 31;
    const int cnt   = min(g_cnt, WLCAP);

    const float AL  = 0.36787944117144233f;
    const float OMB = 1.0f - AL;
    const float thr = thr_p[0];

    for (int it = w; it < cnt; it += nwarp) {
        int lin = g_wl[it];
        int h  = lin & (DH - 1);
        int bt = lin >> 9;
        int t  = bt & (T - 1);
        int b  = bt >> 10;

        int tw = (t >= 80) ? (t - 80) : 0;
        int nT = t - tw + 1;   // <= 81

        const float* wrow = W + (size_t)h * DIN;
        float bh = bias[h];

        float acc[3] = {0.0f, 0.0f, 0.0f};
        bool  vld[3];
        const float* ip[3];
#pragma unroll
        for (int u = 0; u < 3; u++) {
            int tp = tw + lane + u * 32;
            vld[u] = (tp <= t);
            int tsafe = vld[u] ? tp : t;
            ip[u] = X + ((size_t)b * T + tsafe) * DIN;
        }
        for (int k = 0; k < DIN; k += 4) {
            float4 w4 = *(const float4*)(wrow + k);
#pragma unroll
            for (int u = 0; u < 3; u++) {
                float4 a4 = *(const float4*)(ip[u] + k);
                acc[u] = fmaf(a4.x, w4.x, acc[u]);
                acc[u] = fmaf(a4.y, w4.y, acc[u]);
                acc[u] = fmaf(a4.z, w4.z, acc[u]);
                acc[u] = fmaf(a4.w, w4.w, acc[u]);
            }
        }
        float xv[3];
#pragma unroll
        for (int u = 0; u < 3; u++) xv[u] = acc[u] + bh;

        // all lanes run the same scan (redundant, cheap)
        float s = 0.0f, m = 0.0f;
        for (int q = 0; q < nT; q++) {
            float x0 = __shfl_sync(0xFFFFFFFFu, xv[0], q & 31);
            float x1 = __shfl_sync(0xFFFFFFFFu, xv[1], q & 31);
            float x2 = __shfl_sync(0xFFFFFFFFu, xv[2], q & 31);
            float x = (q < 32) ? x0 : ((q < 64) ? x1 : x2);
            s = fmaf(AL, s, x);
            m = fmaf(AL, m, OMB * s);
        }
        if (lane == 0)
            OUT[lin] = (m > thr) ? 1.0f : 0.0f;
    }
}

// ---------------------------------------------------------------------------
extern "C" void kernel_launch(void* const* d_in, const int* in_sizes, int n_in,
                              void* d_out, int out_size)
{
    const float* inputs = (const float*)d_in[0];
    const float* W      = (const float*)d_in[1];
    const float* bias   = (const float*)d_in[2];
    const float* thr    = (const float*)d_in[3];
    float*       out    = (float*)d_out;

    cudaFuncSetAttribute(gemm_int, cudaFuncAttributeMaxDynamicSharedMemorySize, SMEM_BYTES);

    zero_cnt<<<1, 1>>>();
    conv_quant<<<BATCH * 8, 128>>>(inputs);
    w_quant<<<512, 128>>>(W);

    dim3 ggrid(M_TOT / 128, DH / 64);   // (256, 8)
    gemm_int<<<ggrid, 256, SMEM_BYTES>>>(bias, thr, out);

    patch<<<128, 256>>>(inputs, W, bias, thr, out);
}

// round 10
// speedup vs baseline: 2.3848x; 2.3848x over previous
#include <cuda_runtime.h>
#include <cstdint>

#define BATCH 32
#define T     1024
#define DIN   512
#define DH    512
#define M_TOT (BATCH * T)   // 32768

// 64 MB scratch for X = inputs @ W^T + b
__device__ float g_X[(size_t)M_TOT * DH];

// ---------------------------------------------------------------------------
// Blackwell packed fp32 pair FMA: d.lo = a.lo*b.lo + c.lo ; d.hi likewise.
// Exact IEEE fp32 RN per lane -> bitwise identical to two scalar fmaf.
// ---------------------------------------------------------------------------
__device__ __forceinline__ void ffma2(unsigned long long& c,
                                      unsigned long long a,
                                      unsigned long long b) {
    asm("fma.rn.f32x2 %0, %1, %2, %0;" : "+l"(c) : "l"(a), "l"(b));
}
__device__ __forceinline__ float f2lo(unsigned long long u) {
    return __uint_as_float((uint32_t)u);
}
__device__ __forceinline__ float f2hi(unsigned long long u) {
    return __uint_as_float((uint32_t)(u >> 32));
}

// ---------------------------------------------------------------------------
// GEMM: X[m,n] = sum_k A[m,k] * W[n,k] + bias[n]
// Identical math / op-order to the R1 baseline (each acc element accumulates
// k=0..511 ascending with fp32 RN FMA), but packed 2-wide with f32x2.
// 128x128 tile, 256 threads, 8x8 per thread (as 8x4 f32x2 pairs), k-tile 8.
// A stored DUPLICATED in smem ((a,a) pairs) so v2.u64 loads give broadcast
// pairs directly; B stored with +2 pad per 32 floats to break the 4-way
// tx-stride-8 bank conflict (LDS.64 reads, 8B aligned).
// ---------------------------------------------------------------------------
#define ASR 256     // floats per As2 row (128 values duplicated)
#define BSR 136     // floats per Bs row (128 + 8 swizzle pad)

__global__ __launch_bounds__(256, 2)
void gemm_f32x2(const float* __restrict__ A, const float* __restrict__ W,
                const float* __restrict__ bias, float* __restrict__ X)
{
    __shared__ __align__(16) float As2[8][ASR];
    __shared__ __align__(16) float Bs[8][BSR];

    const int tid = threadIdx.x;
    const int tx  = tid & 15;          // n subtile
    const int ty  = tid >> 4;          // m subtile
    const int bm  = blockIdx.x * 128;
    const int bn  = blockIdx.y * 128;
    const int lr  = tid >> 1;          // staging row 0..127
    const int lc  = (tid & 1) << 2;    // staging k offset 0 or 4
    const int bp  = lr + ((lr >> 5) << 1);   // swizzled B column

    unsigned long long acc[8][4];
#pragma unroll
    for (int i = 0; i < 8; i++)
#pragma unroll
        for (int j2 = 0; j2 < 4; j2++) acc[i][j2] = 0ULL;

    const float* ap = A + (size_t)(bm + lr) * DIN + lc;
    const float* wp = W + (size_t)(bn + lr) * DIN + lc;

    for (int k0 = 0; k0 < DIN; k0 += 8) {
        float4 av = *(const float4*)(ap + k0);
        float4 wv = *(const float4*)(wp + k0);
        __syncthreads();
        *(float2*)&As2[lc + 0][2 * lr] = make_float2(av.x, av.x);
        *(float2*)&As2[lc + 1][2 * lr] = make_float2(av.y, av.y);
        *(float2*)&As2[lc + 2][2 * lr] = make_float2(av.z, av.z);
        *(float2*)&As2[lc + 3][2 * lr] = make_float2(av.w, av.w);
        Bs[lc + 0][bp] = wv.x;
        Bs[lc + 1][bp] = wv.y;
        Bs[lc + 2][bp] = wv.z;
        Bs[lc + 3][bp] = wv.w;
        __syncthreads();

#pragma unroll
        for (int k = 0; k < 8; k++) {
            unsigned long long a2[8], b2[4];
#pragma unroll
            for (int q = 0; q < 4; q++) {
                ulonglong2 v = *(const ulonglong2*)&As2[k][ty * 16 + q * 4];
                a2[2 * q]     = v.x;     // (a[ty*8+2q],   a[ty*8+2q])
                a2[2 * q + 1] = v.y;     // (a[ty*8+2q+1], a[ty*8+2q+1])
            }
#pragma unroll
            for (int j2 = 0; j2 < 4; j2++) {
                int n = tx * 8 + j2 * 2;
                b2[j2] = *(const unsigned long long*)&Bs[k][n + ((n >> 5) << 1)];
            }
#pragma unroll
            for (int i = 0; i < 8; i++)
#pragma unroll
                for (int j2 = 0; j2 < 4; j2++)
                    ffma2(acc[i][j2], a2[i], b2[j2]);
        }
    }

    // epilogue: bias add + store (same op order as R1: acc + bv, plain add)
    float bv[8];
#pragma unroll
    for (int j = 0; j < 8; j++) bv[j] = bias[bn + tx * 8 + j];

#pragma unroll
    for (int i = 0; i < 8; i++) {
        float* orow = X + (size_t)(bm + ty * 8 + i) * DH + bn + tx * 8;
        float4 v0, v1;
        v0.x = f2lo(acc[i][0]) + bv[0];
        v0.y = f2hi(acc[i][0]) + bv[1];
        v0.z = f2lo(acc[i][1]) + bv[2];
        v0.w = f2hi(acc[i][1]) + bv[3];
        v1.x = f2lo(acc[i][2]) + bv[4];
        v1.y = f2hi(acc[i][2]) + bv[5];
        v1.z = f2lo(acc[i][3]) + bv[6];
        v1.w = f2hi(acc[i][3]) + bv[7];
        *(float4*)(orow + 0) = v0;
        *(float4*)(orow + 4) = v1;
    }
}

// ---------------------------------------------------------------------------
// Chunk-parallel scan with decay-truncated warmup (96 steps: state influence
// ~(t+1)e^-t -> 1e-40 at 96; bitwise-equal to the full sequential scan with
// probability 1 - ~1e-15 over all elements; mechanism validated in R8).
//   s[t] = a*s[t-1] + X[t];  m[t] = a*m[t-1] + (1-a)*s[t];  out = (m > thr)
// grid = 32 batches x 8 T-chunks x 2 h-halves = 512 blocks x 256 threads.
// ---------------------------------------------------------------------------
__global__ __launch_bounds__(256)
void scan2(const float* __restrict__ X, const float* __restrict__ thr_p,
           float* __restrict__ out)
{
    const int bc    = blockIdx.x;
    const int b     = bc >> 4;          // 0..31
    const int chunk = (bc >> 1) & 7;    // 0..7
    const int half  = bc & 1;
    const int h     = half * 256 + threadIdx.x;

    const float AL  = 0.36787944117144233f;   // exp(-1)
    const float OMB = 1.0f - AL;
    const float thr = thr_p[0];

    const float* xp = X   + (size_t)b * T * DH + h;
    float*       op = out + (size_t)b * T * DH + h;

    const int t0 = chunk * 128;
    const int w0 = (t0 >= 96) ? (t0 - 96) : 0;

    float s = 0.0f, m = 0.0f;

    for (int t = w0; t < t0; t += 8) {
        float x[8];
#pragma unroll
        for (int u = 0; u < 8; u++) x[u] = xp[(size_t)(t + u) * DH];
#pragma unroll
        for (int u = 0; u < 8; u++) {
            s = fmaf(AL, s, x[u]);
            m = fmaf(AL, m, OMB * s);
        }
    }
    for (int t = t0; t < t0 + 128; t += 8) {
        float x[8], sp[8];
#pragma unroll
        for (int u = 0; u < 8; u++) x[u] = xp[(size_t)(t + u) * DH];
#pragma unroll
        for (int u = 0; u < 8; u++) {
            s = fmaf(AL, s, x[u]);
            m = fmaf(AL, m, OMB * s);
            sp[u] = (m > thr) ? 1.0f : 0.0f;
        }
#pragma unroll
        for (int u = 0; u < 8; u++) op[(size_t)(t + u) * DH] = sp[u];
    }
}

// ---------------------------------------------------------------------------
extern "C" void kernel_launch(void* const* d_in, const int* in_sizes, int n_in,
                              void* d_out, int out_size)
{
    const float* inputs = (const float*)d_in[0];  // (32, 1024, 512)
    const float* W      = (const float*)d_in[1];  // (512, 512)
    const float* bias   = (const float*)d_in[2];  // (512,)
    const float* thr    = (const float*)d_in[3];  // scalar
    float*       out    = (float*)d_out;          // (32, 1024, 512)

    float* Xs;
    cudaGetSymbolAddress((void**)&Xs, g_X);

    dim3 ggrid(M_TOT / 128, DH / 128);   // (256, 4)
    gemm_f32x2<<<ggrid, 256>>>(inputs, W, bias, Xs);

    scan2<<<512, 256>>>(Xs, thr, out);
}